// round 1
// baseline (speedup 1.0000x reference)
#include <cuda_runtime.h>

// Problem constants: B=4, S=256, D_MODEL=2048, H=256, HEAD_DIM=8
#define MROWS 1024      // B*S
#define DM    2048
#define NHEAD 256
#define HD    8
#define ATTN_SCALE 0.35355339059327373f   // 1/sqrt(8)

// Scratch (no allocations allowed in kernel_launch)
__device__ float g_q[MROWS * DM];
__device__ float g_k[MROWS * DM];
__device__ float g_v[MROWS * DM];
__device__ float g_att[MROWS * DM];

// ---------------------------------------------------------------------------
// Tiled SGEMM: C(1024x2048) = A(1024x2048) @ B(2048x2048) + bias(2048)
// BM=BN=128, BK=16, 256 threads, 8x8 microtile per thread.
// ---------------------------------------------------------------------------
#define BM 128
#define BN 128
#define BK 16
#define TM 8
#define TN 8
#define GK 2048
#define GN 2048

__device__ __forceinline__ void gemm_body(const float* __restrict__ A,
                                          const float* __restrict__ B,
                                          const float* __restrict__ bias,
                                          float* __restrict__ C)
{
    __shared__ float As[BK][BM];   // A tile stored transposed
    __shared__ float Bs[BK][BN];

    const int tid = threadIdx.x;
    const int tx  = tid & 15;          // N direction (16 threads)
    const int ty  = tid >> 4;          // M direction (16 threads)
    const int row0 = blockIdx.y * BM;
    const int col0 = blockIdx.x * BN;

    float acc[TM][TN];
#pragma unroll
    for (int i = 0; i < TM; i++)
#pragma unroll
        for (int j = 0; j < TN; j++) acc[i][j] = 0.f;

    for (int k0 = 0; k0 < GK; k0 += BK) {
        // Load A tile 128x16 (2 float4 per thread), store transposed.
#pragma unroll
        for (int l = 0; l < 2; l++) {
            int f   = tid + l * 256;        // float4 index 0..511
            int ar  = f >> 2;               // row within tile 0..127
            int ac4 = (f & 3) << 2;         // k offset 0,4,8,12
            float4 v4 = *reinterpret_cast<const float4*>(
                &A[(size_t)(row0 + ar) * GK + k0 + ac4]);
            As[ac4 + 0][ar] = v4.x;
            As[ac4 + 1][ar] = v4.y;
            As[ac4 + 2][ar] = v4.z;
            As[ac4 + 3][ar] = v4.w;
        }
        // Load B tile 16x128 (2 float4 per thread).
#pragma unroll
        for (int l = 0; l < 2; l++) {
            int f   = tid + l * 256;
            int br  = f >> 5;               // row 0..15
            int bc4 = (f & 31) << 2;        // col offset 0..124
            *reinterpret_cast<float4*>(&Bs[br][bc4]) =
                *reinterpret_cast<const float4*>(
                    &B[(size_t)(k0 + br) * GN + col0 + bc4]);
        }
        __syncthreads();

#pragma unroll
        for (int kk = 0; kk < BK; kk++) {
            float ra[TM], rb[TN];
            float4 a0 = *reinterpret_cast<const float4*>(&As[kk][ty * TM]);
            float4 a1 = *reinterpret_cast<const float4*>(&As[kk][ty * TM + 4]);
            ra[0] = a0.x; ra[1] = a0.y; ra[2] = a0.z; ra[3] = a0.w;
            ra[4] = a1.x; ra[5] = a1.y; ra[6] = a1.z; ra[7] = a1.w;
            float4 b0 = *reinterpret_cast<const float4*>(&Bs[kk][tx * TN]);
            float4 b1 = *reinterpret_cast<const float4*>(&Bs[kk][tx * TN + 4]);
            rb[0] = b0.x; rb[1] = b0.y; rb[2] = b0.z; rb[3] = b0.w;
            rb[4] = b1.x; rb[5] = b1.y; rb[6] = b1.z; rb[7] = b1.w;
#pragma unroll
            for (int i = 0; i < TM; i++)
#pragma unroll
                for (int j = 0; j < TN; j++)
                    acc[i][j] = fmaf(ra[i], rb[j], acc[i][j]);
        }
        __syncthreads();
    }

    // Epilogue: add bias, store with float4.
#pragma unroll
    for (int i = 0; i < TM; i++) {
        int r = row0 + ty * TM + i;
        float* crow = &C[(size_t)r * GN + col0 + tx * TN];
        const float* brow = &bias[col0 + tx * TN];
#pragma unroll
        for (int j = 0; j < TN; j += 4) {
            float4 bv = *reinterpret_cast<const float4*>(brow + j);
            float4 o;
            o.x = acc[i][j + 0] + bv.x;
            o.y = acc[i][j + 1] + bv.y;
            o.z = acc[i][j + 2] + bv.z;
            o.w = acc[i][j + 3] + bv.w;
            *reinterpret_cast<float4*>(crow + j) = o;
        }
    }
}

// Fused QKV projection: grid.z selects which of the three GEMMs to compute.
__global__ __launch_bounds__(256)
void qkv_gemm_kernel(const float* __restrict__ x,
                     const float* __restrict__ Wq, const float* __restrict__ bq,
                     const float* __restrict__ Wk, const float* __restrict__ bk,
                     const float* __restrict__ Wv, const float* __restrict__ bv)
{
    if (blockIdx.z == 0)      gemm_body(x, Wq, bq, g_q);
    else if (blockIdx.z == 1) gemm_body(x, Wk, bk, g_k);
    else                      gemm_body(x, Wv, bv, g_v);
}

// Output projection: out = g_att @ Wo + bo
__global__ __launch_bounds__(256)
void out_gemm_kernel(const float* __restrict__ Wo, const float* __restrict__ bo,
                     float* __restrict__ out)
{
    gemm_body(g_att, Wo, bo, out);
}

// ---------------------------------------------------------------------------
// Attention: one CTA per (b,s) row. Q,K,V slices are 256 heads x 8 dims.
// Phase rotation cancels analytically: logits = (q.k)/sqrt(8); si == 0 and
// attn_i is discarded, so phase_shift never reaches the output.
// One thread per head; single-pass softmax (logits are O(+-10), no max needed).
// ---------------------------------------------------------------------------
__global__ __launch_bounds__(256)
void attn_kernel()
{
    __shared__ float sq[NHEAD * HD];
    __shared__ float sk[NHEAD * HD];
    __shared__ float sv[NHEAD * HD];

    const int m = blockIdx.x;            // (b*S + s)
    const int t = threadIdx.x;           // head index

    const float4* qg = reinterpret_cast<const float4*>(g_q + (size_t)m * DM);
    const float4* kg = reinterpret_cast<const float4*>(g_k + (size_t)m * DM);
    const float4* vg = reinterpret_cast<const float4*>(g_v + (size_t)m * DM);
#pragma unroll
    for (int l = 0; l < 2; l++) {
        int i = t + l * 256;             // 512 float4 per tensor
        reinterpret_cast<float4*>(sq)[i] = qg[i];
        reinterpret_cast<float4*>(sk)[i] = kg[i];
        reinterpret_cast<float4*>(sv)[i] = vg[i];
    }
    __syncthreads();

    float qh[HD];
#pragma unroll
    for (int d = 0; d < HD; d++) qh[d] = sq[t * HD + d];

    float l = 0.f;
    float accd[HD];
#pragma unroll
    for (int d = 0; d < HD; d++) accd[d] = 0.f;

    for (int g = 0; g < NHEAD; g++) {
        const float* kr = &sk[g * HD];
        float s = 0.f;
#pragma unroll
        for (int d = 0; d < HD; d++) s = fmaf(qh[d], kr[d], s);
        float p = __expf(s * ATTN_SCALE);
        l += p;
        const float* vr = &sv[g * HD];
#pragma unroll
        for (int d = 0; d < HD; d++) accd[d] = fmaf(p, vr[d], accd[d]);
    }

    float inv = 1.f / l;
    float4 o0, o1;
    o0.x = accd[0] * inv; o0.y = accd[1] * inv; o0.z = accd[2] * inv; o0.w = accd[3] * inv;
    o1.x = accd[4] * inv; o1.y = accd[5] * inv; o1.z = accd[6] * inv; o1.w = accd[7] * inv;
    float* orow = g_att + (size_t)m * DM + t * HD;
    *reinterpret_cast<float4*>(orow)     = o0;
    *reinterpret_cast<float4*>(orow + 4) = o1;
}

// ---------------------------------------------------------------------------
// Launch
// ---------------------------------------------------------------------------
extern "C" void kernel_launch(void* const* d_in, const int* in_sizes, int n_in,
                              void* d_out, int out_size)
{
    const float* x  = (const float*)d_in[0];
    // d_in[1] = phase_shift: cancels analytically, unused.
    const float* Wq = (const float*)d_in[2];
    const float* bq = (const float*)d_in[3];
    const float* Wk = (const float*)d_in[4];
    const float* bk = (const float*)d_in[5];
    const float* Wv = (const float*)d_in[6];
    const float* bv = (const float*)d_in[7];
    const float* Wo = (const float*)d_in[8];
    const float* bo = (const float*)d_in[9];
    float* out = (float*)d_out;

    dim3 gemm_grid(GN / BN, MROWS / BM);          // (16, 8)
    dim3 qkv_grid(GN / BN, MROWS / BM, 3);        // (16, 8, 3)

    qkv_gemm_kernel<<<qkv_grid, 256>>>(x, Wq, bq, Wk, bk, Wv, bv);
    attn_kernel<<<MROWS, 256>>>();                // reads g_q/g_k/g_v, writes g_att
    out_gemm_kernel<<<gemm_grid, 256>>>(Wo, bo, out);
}

// round 4
// speedup vs baseline: 2.8064x; 2.8064x over previous
#include <cuda_runtime.h>
#include <cstdint>

// Problem constants: B=4, S=256, D_MODEL=2048, H=256, HEAD_DIM=8
#define DM     2048
#define MROWS  1024
#define NHEAD  256
#define HD     8
#define ATTN_SCALE 0.35355339059327373f   // 1/sqrt(8)

// ---- mma.sync tf32 GEMM tiling ----
#define BMT 128                 // CTA tile M
#define BNT 128                 // CTA tile N
#define BKT 32                  // CTA tile K (tf32 elems)
#define NKT (DM / BKT)          // 64 k-tiles
#define APAD 36                 // padded row stride (floats): conflict-free frags
#define TILE_FLOATS (128 * APAD)          // per operand per stage
#define SMEM_FLOATS (4 * TILE_FLOATS)     // A0,A1,B0,B1
#define SMEM_BYTES  (SMEM_FLOATS * 4)     // 73728

// ---- device scratch ----
__device__ float g_xr[MROWS * DM];      // tf32-rounded x
__device__ float g_wt[4][DM * DM];      // W^T [N][K], tf32-rounded: Wq,Wk,Wv,Wo
__device__ float g_q[MROWS * DM];
__device__ float g_k[MROWS * DM];
__device__ float g_v[MROWS * DM];
__device__ float g_att[MROWS * DM];     // tf32-rounded attention output

// ---------------------------------------------------------------------------
// helpers
// ---------------------------------------------------------------------------
__device__ __forceinline__ uint32_t smem_u32(const void* p) {
    uint32_t a;
    asm("{ .reg .u64 t; cvta.to.shared.u64 t, %1; cvt.u32.u64 %0, t; }" : "=r"(a) : "l"(p));
    return a;
}
__device__ __forceinline__ float tf32r(float x) {
    uint32_t u;
    asm("cvt.rna.tf32.f32 %0, %1;" : "=r"(u) : "f"(x));
    return __uint_as_float(u);
}
__device__ __forceinline__ void cp_async16(uint32_t dst, const void* src) {
    asm volatile("cp.async.cg.shared.global [%0], [%1], 16;" :: "r"(dst), "l"(src));
}
#define CP_COMMIT() asm volatile("cp.async.commit_group;" ::: "memory")
#define CP_WAIT(n)  asm volatile("cp.async.wait_group %0;" :: "n"(n) : "memory")

__device__ __forceinline__ void mma_1688(float c[4], const uint32_t a[4], const uint32_t b[2]) {
    asm volatile(
        "mma.sync.aligned.m16n8k8.row.col.f32.tf32.tf32.f32 "
        "{%0,%1,%2,%3}, {%4,%5,%6,%7}, {%8,%9}, {%0,%1,%2,%3};"
        : "+f"(c[0]), "+f"(c[1]), "+f"(c[2]), "+f"(c[3])
        : "r"(a[0]), "r"(a[1]), "r"(a[2]), "r"(a[3]), "r"(b[0]), "r"(b[1]));
}

// ---------------------------------------------------------------------------
// tf32 tensor-core GEMM: C[128,128] tile = A @ B^T + bias
// A: [1024,2048] row-major (M x K).  Bw = W^T: [2048,2048] row-major (N x K).
// 256 threads, 8 warps: warp grid 2(M) x 4(N), warp tile 64 x 32.
// Both smem operands row-major with APAD=36 stride -> conflict-free LDS frags.
// ---------------------------------------------------------------------------
__device__ __forceinline__ void gemm_body(const float* __restrict__ A,
                                          const float* __restrict__ Bw,
                                          const float* __restrict__ bias,
                                          float* __restrict__ C)
{
    extern __shared__ float sm[];
    float* const Asm = sm;                        // [2][TILE_FLOATS]
    float* const Bsm = sm + 2 * TILE_FLOATS;      // [2][TILE_FLOATS]

    const int tid  = threadIdx.x;
    const int wid  = tid >> 5;
    const int lane = tid & 31;
    const int tg   = lane >> 2;      // 0..7 (fragment group)
    const int tr   = lane & 3;       // 0..3 (in-group)
    const int m0   = (wid & 1) * 64; // warp M offset
    const int n0   = (wid >> 1) * 32;// warp N offset
    const int row0 = blockIdx.y * BMT;
    const int col0 = blockIdx.x * BNT;

    const float* gA = A  + (size_t)row0 * DM;
    const float* gB = Bw + (size_t)col0 * DM;

    float acc[4][4][4];
#pragma unroll
    for (int mt = 0; mt < 4; mt++)
#pragma unroll
        for (int nt = 0; nt < 4; nt++)
#pragma unroll
            for (int i = 0; i < 4; i++) acc[mt][nt][i] = 0.f;

    // per-thread cp.async slots: 4 chunks of A + 4 of B per stage
    const int cr = tid >> 1;                 // row pair base: rows cr, cr+? (see below)
    // chunk index c = tid + i*256 ; row = c>>3 (0..127), q = c&7 (16B chunk in row)
#define PREFETCH(kt, s)                                                          \
    do {                                                                         \
        float* da = Asm + (s) * TILE_FLOATS;                                     \
        float* db = Bsm + (s) * TILE_FLOATS;                                     \
        const float* sa = gA + (kt) * BKT;                                       \
        const float* sb = gB + (kt) * BKT;                                       \
        _Pragma("unroll")                                                        \
        for (int i = 0; i < 4; i++) {                                            \
            int c4 = tid + i * 256;                                              \
            int r = c4 >> 3, q = c4 & 7;                                         \
            cp_async16(smem_u32(da + r * APAD + q * 4), sa + (size_t)r * DM + q * 4); \
            cp_async16(smem_u32(db + r * APAD + q * 4), sb + (size_t)r * DM + q * 4); \
        }                                                                        \
    } while (0)

    PREFETCH(0, 0);
    CP_COMMIT();

    for (int kt = 0; kt < NKT; kt++) {
        if (kt + 1 < NKT) {
            PREFETCH(kt + 1, (kt + 1) & 1);
            CP_COMMIT();
            CP_WAIT(1);
        } else {
            CP_WAIT(0);
        }
        __syncthreads();

        const float* a = Asm + (kt & 1) * TILE_FLOATS;
        const float* b = Bsm + (kt & 1) * TILE_FLOATS;
#pragma unroll
        for (int ks = 0; ks < 4; ks++) {
            const int k0 = ks * 8;
            uint32_t af[4][4], bf[4][2];
#pragma unroll
            for (int mt = 0; mt < 4; mt++) {
                const float* ap = a + (m0 + mt * 16 + tg) * APAD + k0 + tr;
                af[mt][0] = __float_as_uint(ap[0]);
                af[mt][1] = __float_as_uint(ap[8 * APAD]);
                af[mt][2] = __float_as_uint(ap[4]);
                af[mt][3] = __float_as_uint(ap[8 * APAD + 4]);
            }
#pragma unroll
            for (int nt = 0; nt < 4; nt++) {
                const float* bp = b + (n0 + nt * 8 + tg) * APAD + k0 + tr;
                bf[nt][0] = __float_as_uint(bp[0]);
                bf[nt][1] = __float_as_uint(bp[4]);
            }
#pragma unroll
            for (int mt = 0; mt < 4; mt++)
#pragma unroll
                for (int nt = 0; nt < 4; nt++)
                    mma_1688(acc[mt][nt], af[mt], bf[nt]);
        }
        __syncthreads();
    }
    (void)cr;

    // Epilogue: c0/c1 -> (row, 2*tr), (row, 2*tr+1); c2/c3 -> row+8
#pragma unroll
    for (int mt = 0; mt < 4; mt++) {
        const int r1 = row0 + m0 + mt * 16 + tg;
        const int r2 = r1 + 8;
#pragma unroll
        for (int nt = 0; nt < 4; nt++) {
            const int cb = col0 + n0 + nt * 8 + 2 * tr;
            const float2 bv = *reinterpret_cast<const float2*>(bias + cb);
            float2 o1, o2;
            o1.x = acc[mt][nt][0] + bv.x; o1.y = acc[mt][nt][1] + bv.y;
            o2.x = acc[mt][nt][2] + bv.x; o2.y = acc[mt][nt][3] + bv.y;
            *reinterpret_cast<float2*>(C + (size_t)r1 * DM + cb) = o1;
            *reinterpret_cast<float2*>(C + (size_t)r2 * DM + cb) = o2;
        }
    }
#undef PREFETCH
}

__global__ __launch_bounds__(256)
void qkv_tc(const float* __restrict__ bq, const float* __restrict__ bk,
            const float* __restrict__ bv)
{
    const int z = blockIdx.z;
    const float* bias = (z == 0) ? bq : (z == 1) ? bk : bv;
    float* C = (z == 0) ? g_q : (z == 1) ? g_k : g_v;
    gemm_body(g_xr, g_wt[z], bias, C);
}

__global__ __launch_bounds__(256)
void out_tc(const float* __restrict__ bo, float* __restrict__ out)
{
    gemm_body(g_att, g_wt[3], bo, out);
}

// ---------------------------------------------------------------------------
// W[K,N] -> W^T[N,K] with tf32 round-to-nearest
// ---------------------------------------------------------------------------
__global__ __launch_bounds__(256)
void transpose_round(const float* __restrict__ W0, const float* __restrict__ W1,
                     const float* __restrict__ W2, const float* __restrict__ W3)
{
    __shared__ float tile[32][33];
    const float* W = (blockIdx.z == 0) ? W0 : (blockIdx.z == 1) ? W1
                   : (blockIdx.z == 2) ? W2 : W3;
    float* T = g_wt[blockIdx.z];
    const int x0 = blockIdx.x * 32;     // N direction in W
    const int y0 = blockIdx.y * 32;     // K direction in W
    const int tx = threadIdx.x & 31;
    const int ty = threadIdx.x >> 5;    // 0..7
#pragma unroll
    for (int i = 0; i < 4; i++)
        tile[ty + i * 8][tx] = W[(size_t)(y0 + ty + i * 8) * DM + x0 + tx];
    __syncthreads();
#pragma unroll
    for (int i = 0; i < 4; i++)
        T[(size_t)(x0 + ty + i * 8) * DM + y0 + tx] = tf32r(tile[tx][ty + i * 8]);
}

// x -> tf32-rounded copy
__global__ __launch_bounds__(256)
void convert_x(const float* __restrict__ x)
{
    const int n4 = MROWS * DM / 4;
    for (int i = blockIdx.x * blockDim.x + threadIdx.x; i < n4; i += gridDim.x * blockDim.x) {
        float4 v = reinterpret_cast<const float4*>(x)[i];
        v.x = tf32r(v.x); v.y = tf32r(v.y); v.z = tf32r(v.z); v.w = tf32r(v.w);
        reinterpret_cast<float4*>(g_xr)[i] = v;
    }
}

// ---------------------------------------------------------------------------
// Attention: one CTA per (b,s) row, one thread per head.
// Phase rotation cancels analytically: logits = (q.k)/sqrt(8); si == 0 and
// attn_i is discarded, so phase_shift never reaches the output.
// Output tf32-rounded (feeds the out-projection MMA).
// ---------------------------------------------------------------------------
__global__ __launch_bounds__(256)
void attn_kernel()
{
    __shared__ float4 sk[NHEAD * 2];
    __shared__ float4 sv[NHEAD * 2];
    const int m = blockIdx.x;
    const int t = threadIdx.x;

    const float4* kg = reinterpret_cast<const float4*>(g_k + (size_t)m * DM);
    const float4* vg = reinterpret_cast<const float4*>(g_v + (size_t)m * DM);
    sk[t] = kg[t]; sk[t + 256] = kg[t + 256];
    sv[t] = vg[t]; sv[t + 256] = vg[t + 256];
    __syncthreads();

    const float4* qg = reinterpret_cast<const float4*>(g_q + (size_t)m * DM);
    float4 q0 = qg[2 * t], q1 = qg[2 * t + 1];

    float l = 0.f;
    float4 a0 = {0.f, 0.f, 0.f, 0.f}, a1 = {0.f, 0.f, 0.f, 0.f};

    for (int g = 0; g < NHEAD; g++) {
        float4 k0 = sk[2 * g], k1 = sk[2 * g + 1];
        float s = q0.x * k0.x + q0.y * k0.y + q0.z * k0.z + q0.w * k0.w
                + q1.x * k1.x + q1.y * k1.y + q1.z * k1.z + q1.w * k1.w;
        float p = __expf(s * ATTN_SCALE);
        l += p;
        float4 v0 = sv[2 * g], v1 = sv[2 * g + 1];
        a0.x = fmaf(p, v0.x, a0.x); a0.y = fmaf(p, v0.y, a0.y);
        a0.z = fmaf(p, v0.z, a0.z); a0.w = fmaf(p, v0.w, a0.w);
        a1.x = fmaf(p, v1.x, a1.x); a1.y = fmaf(p, v1.y, a1.y);
        a1.z = fmaf(p, v1.z, a1.z); a1.w = fmaf(p, v1.w, a1.w);
    }

    const float inv = 1.f / l;
    float4 o0, o1;
    o0.x = tf32r(a0.x * inv); o0.y = tf32r(a0.y * inv);
    o0.z = tf32r(a0.z * inv); o0.w = tf32r(a0.w * inv);
    o1.x = tf32r(a1.x * inv); o1.y = tf32r(a1.y * inv);
    o1.z = tf32r(a1.z * inv); o1.w = tf32r(a1.w * inv);
    float4* orow = reinterpret_cast<float4*>(g_att + (size_t)m * DM + t * HD);
    orow[0] = o0;
    orow[1] = o1;
}

// ---------------------------------------------------------------------------
// Launch
// ---------------------------------------------------------------------------
extern "C" void kernel_launch(void* const* d_in, const int* in_sizes, int n_in,
                              void* d_out, int out_size)
{
    const float* x  = (const float*)d_in[0];
    // d_in[1] = phase_shift: cancels analytically, unused.
    const float* Wq = (const float*)d_in[2];
    const float* bq = (const float*)d_in[3];
    const float* Wk = (const float*)d_in[4];
    const float* bk = (const float*)d_in[5];
    const float* Wv = (const float*)d_in[6];
    const float* bv = (const float*)d_in[7];
    const float* Wo = (const float*)d_in[8];
    const float* bo = (const float*)d_in[9];
    float* out = (float*)d_out;

    cudaFuncSetAttribute(qkv_tc, cudaFuncAttributeMaxDynamicSharedMemorySize, SMEM_BYTES);
    cudaFuncSetAttribute(out_tc, cudaFuncAttributeMaxDynamicSharedMemorySize, SMEM_BYTES);

    convert_x<<<512, 256>>>(x);
    transpose_round<<<dim3(DM / 32, DM / 32, 4), 256>>>(Wq, Wk, Wv, Wo);

    dim3 qkv_grid(DM / BNT, MROWS / BMT, 3);     // (16, 8, 3)
    qkv_tc<<<qkv_grid, 256, SMEM_BYTES>>>(bq, bk, bv);

    attn_kernel<<<MROWS, 256>>>();

    dim3 out_grid(DM / BNT, MROWS / BMT);        // (16, 8)
    out_tc<<<out_grid, 256, SMEM_BYTES>>>(bo, out);
}